// round 15
// baseline (speedup 1.0000x reference)
#include <cuda_runtime.h>
#include <cuda_fp16.h>
#include <cstdint>
#include <cstddef>

// ============================================================================
// BinConv2d: BN(train stats) -> sign -> conv3x3(64->64,pad1) -> +bias -> ReLU
//   x:[32,64,112,112] f32 -> out same shape f32.
// sm_103-safe (harness compiles at compute_103: no tcgen05):
//   mma.sync.m16n8k16 f16 implicit GEMM (measured at its structural floor:
//   rt_eff ~13 cyc/SMSP for f32-acc HMMA on sm_103a).
// 4 launches (each component at its measured-best configuration):
//   k_stats : per-(c,n) partials, 12-deep LDG batches (19.9us, 67% DRAM)
//   k_final : per-channel scale/shift + work-steal counter reset (~1us;
//             fusing this anywhere else measured slower 3x: R10/R12/R14)
//   k_prep  : blocks 0-17 wprep; rest binarize one row from g_ss (~20us)
//   k_conv  : persistent 256thr work-stealing conv (86us, mma.sync floor)
// ============================================================================

#define N_IMG 32
#define HH    112
#define WW    112
#define HP    114
#define PIX   (HH*WW)            // 12544
#define NTILE 1568               // 32 n * 7 th * 7 tw  (16x16 px tiles)

#define B_BYTES    73728         // 9 taps * 4 ksteps * 4 jpairs * 32 lanes * 16B
#define HALO_BYTES 41472         // 18 rows * 18 px * 128B
#define OFF_B      0
#define OFF_H0     (OFF_B + B_BYTES)       // 73728
#define OFF_H1     (OFF_H0 + HALO_BYTES)   // 115200
#define OFF_MBAR   (OFF_H1 + HALO_BYTES)   // 156672
#define SMEM_TOTAL (OFF_MBAR + 16)         // 156688

// ---- scratch (device globals; no runtime allocation) ----
__device__ __align__(1024) __half g_xb[(size_t)N_IMG*HP*HP*64]; // 53.2MB
__device__ __align__(1024) unsigned char g_B[B_BYTES];
__device__ float2 g_part[64*32];
__device__ float2 g_ss[64];
__device__ unsigned g_tile;

// ============================ PTX helpers ===================================
static __device__ __forceinline__ uint32_t smem_u32(const void* p) {
    uint32_t a;
    asm("{ .reg .u64 t; cvta.to.shared.u64 t, %1; cvt.u32.u64 %0, t; }"
        : "=r"(a) : "l"(p));
    return a;
}

#define MBAR_INIT(mbar, cnt) \
    asm volatile("mbarrier.init.shared.b64 [%0], %1;" :: "r"(mbar), "r"(cnt) : "memory")

#define MBAR_EXPECT_TX(mbar, bytes) \
    asm volatile("mbarrier.arrive.expect_tx.shared.b64 _, [%0], %1;" \
                 :: "r"(mbar), "r"(bytes) : "memory")

#define MBAR_WAIT(mbar, ph) do {                                            \
    asm volatile("{\n\t.reg .pred P;\n\t"                                   \
        "WL%=:\n\t"                                                         \
        "mbarrier.try_wait.parity.acquire.cta.shared::cta.b64 P, [%0], %1, 0x989680;\n\t" \
        "@P bra.uni WD%=;\n\t"                                              \
        "bra.uni WL%=;\n\t"                                                 \
        "WD%=:\n\t}"                                                        \
        :: "r"(mbar), "r"((unsigned)(ph)) : "memory");                      \
} while (0)

#define BULK_G2S(dst, src, size, mbar) \
    asm volatile("cp.async.bulk.shared::cta.global.mbarrier::complete_tx::bytes [%0], [%1], %2, [%3];" \
                 :: "r"(dst), "l"(src), "r"(size), "r"(mbar) : "memory")

#define LDSM_X4(r, addr) \
    asm volatile("ldmatrix.sync.aligned.m8n8.x4.shared.b16 {%0,%1,%2,%3}, [%4];" \
        : "=r"((r)[0]),"=r"((r)[1]),"=r"((r)[2]),"=r"((r)[3]) : "r"(addr))

#define LDS128(v0,v1,v2,v3,addr) \
    asm volatile("ld.shared.v4.b32 {%0,%1,%2,%3}, [%4];" \
        : "=r"(v0),"=r"(v1),"=r"(v2),"=r"(v3) : "r"(addr))

#define MMA4(d, a, b0, b1) \
    asm volatile("mma.sync.aligned.m16n8k16.row.col.f32.f16.f16.f32 " \
        "{%0,%1,%2,%3}, {%4,%5,%6,%7}, {%8,%9}, {%0,%1,%2,%3};" \
        : "+f"((d)[0]),"+f"((d)[1]),"+f"((d)[2]),"+f"((d)[3]) \
        : "r"((a)[0]),"r"((a)[1]),"r"((a)[2]),"r"((a)[3]), "r"(b0),"r"(b1))

// ============================ stats kernel ==================================
// 12 independent float4 loads batched per thread (MLP 12), then reduce.

__global__ void k_stats(const float* __restrict__ x) {
    int c = blockIdx.x, n = blockIdx.y;
    const int tid = threadIdx.x;
    const float4* p = (const float4*)(x + ((size_t)(n*64 + c)) * PIX);

    float4 a[12];
    #pragma unroll
    for (int k = 0; k < 12; k++) a[k] = p[k*256 + tid];

    float s0 = 0.f, s1 = 0.f, s2 = 0.f, s3 = 0.f;
    float q0 = 0.f, q1 = 0.f, q2 = 0.f, q3 = 0.f;
    #pragma unroll
    for (int k = 0; k < 12; k += 4) {
        float4 a0 = a[k], a1 = a[k+1], a2 = a[k+2], a3 = a[k+3];
        s0 += a0.x + a0.y + a0.z + a0.w;
        q0 += a0.x*a0.x + a0.y*a0.y + a0.z*a0.z + a0.w*a0.w;
        s1 += a1.x + a1.y + a1.z + a1.w;
        q1 += a1.x*a1.x + a1.y*a1.y + a1.z*a1.z + a1.w*a1.w;
        s2 += a2.x + a2.y + a2.z + a2.w;
        q2 += a2.x*a2.x + a2.y*a2.y + a2.z*a2.z + a2.w*a2.w;
        s3 += a3.x + a3.y + a3.z + a3.w;
        q3 += a3.x*a3.x + a3.y*a3.y + a3.z*a3.z + a3.w*a3.w;
    }
    if (tid < 64) {                                 // 3136 = 12*256 + 64
        float4 r = p[3072 + tid];
        s0 += r.x + r.y + r.z + r.w;
        q0 += r.x*r.x + r.y*r.y + r.z*r.z + r.w*r.w;
    }
    float s = (s0 + s1) + (s2 + s3);
    float q = (q0 + q1) + (q2 + q3);
    #pragma unroll
    for (int o = 16; o > 0; o >>= 1) {
        s += __shfl_down_sync(0xFFFFFFFFu, s, o);
        q += __shfl_down_sync(0xFFFFFFFFu, q, o);
    }
    __shared__ float ws[8], wq[8];
    if ((tid & 31) == 0) { ws[tid >> 5] = s; wq[tid >> 5] = q; }
    __syncthreads();
    if (tid < 8) {
        s = ws[tid]; q = wq[tid];
        #pragma unroll
        for (int o = 4; o > 0; o >>= 1) {
            s += __shfl_down_sync(0xFFu, s, o);
            q += __shfl_down_sync(0xFFu, q, o);
        }
        if (tid == 0) g_part[c*32 + n] = make_float2(s, q);
    }
}

__global__ void k_final(const float* __restrict__ gamma, const float* __restrict__ beta) {
    int c = threadIdx.x;
    if (c == 0) g_tile = 0u;          // reset conv work-steal counter each replay
    if (c >= 64) return;
    float s = 0.f, q = 0.f;
    #pragma unroll 4
    for (int n = 0; n < 32; n++) { float2 p = g_part[c*32 + n]; s += p.x; q += p.y; }
    const float inv = 1.0f / (float)(32*PIX);
    float mean = s * inv;
    float var  = q * inv - mean*mean;     // biased var, matches reference
    float sc = gamma[c] / sqrtf(var + 1e-4f);
    g_ss[c] = make_float2(sc, beta[c] - mean*sc);
}

// ============================ prep kernel ===================================
// blocks 0..17: weight prep.  blocks 18..: binarize one padded row.

static __device__ __forceinline__ void wprep_unit(int u, int tid, const float* Wt) {
    int idx = u*256 + tid;
    int lane = idx & 31, j = (idx>>5)&3, kc = (idx>>7)&3, tap = idx>>9;
    int gid = lane >> 2, tig = lane & 3;
    uint32_t o4[4];
    #pragma unroll
    for (int s2 = 0; s2 < 2; s2++) {
        int n = (j*2 + s2)*8 + gid;
        #pragma unroll
        for (int p = 0; p < 2; p++) {
            uint32_t pr = 0;
            #pragma unroll
            for (int e = 0; e < 2; e++) {
                int kch = kc*16 + tig*2 + e + p*8;
                float w = Wt[((size_t)n*64 + kch)*9 + tap];
                __half v = __float2half(w);
                unsigned short us = *(unsigned short*)&v;
                pr |= (uint32_t)us << (e*16);
            }
            o4[s2*2 + p] = pr;
        }
    }
    *(uint4*)(g_B + (size_t)(((tap*4 + kc)*4 + j)*512) + (size_t)lane*16)
        = make_uint4(o4[0], o4[1], o4[2], o4[3]);
}

__global__ void __launch_bounds__(256)
k_prep(const float* __restrict__ x, const float* __restrict__ Wt) {
    const int tid = threadIdx.x;
    if (blockIdx.x < 18) { wprep_unit(blockIdx.x, tid, Wt); return; }

    const int v = blockIdx.x - 18;
    const int n = v / HP, hp = v % HP;
    uint32_t* dst = (uint32_t*)(g_xb + ((size_t)(n*HP + hp)) * HP * 64);
    if (hp == 0 || hp == HP-1) {
        for (int i = tid; i < HP*32; i += 256) dst[i] = 0u;
        return;
    }
    __shared__ float s[64][113];
    __shared__ float2 ss[64];
    if (tid < 64) ss[tid] = g_ss[tid];
    const int h = hp - 1;
    const float* src = x + ((size_t)n*64) * PIX + (size_t)h * WW;
    for (int i = tid; i < 64*WW; i += 256) {
        int c = i / WW, w = i % WW;
        s[c][w] = __ldcs(&src[(size_t)c * PIX + w]);   // streaming: protect L2
    }
    __syncthreads();
    if (tid < 64) {                       // zero border cols wp=0, wp=113
        int cp = tid & 31;
        int wp = (tid < 32) ? 0 : (HP-1);
        dst[wp*32 + cp] = 0u;
    }
    for (int i = tid; i < WW*32; i += 256) {
        int w = i >> 5, cp = i & 31, c = cp*2;
        float2 p0 = ss[c], p1 = ss[c+1];
        float v0 = s[c][w]   * p0.x + p0.y;
        float v1 = s[c+1][w] * p1.x + p1.y;
        uint32_t u0 = v0 > 0.f ? 0x3C00u : (v0 < 0.f ? 0xBC00u : 0u);  // fp16 +-1
        uint32_t u1 = v1 > 0.f ? 0x3C00u : (v1 < 0.f ? 0xBC00u : 0u);
        int wp = w + 1;
        int pos = (((cp>>2) ^ (wp & 7)) << 2) | (cp & 3);
        dst[wp*32 + pos] = u0 | (u1 << 16);
    }
}

// ============================ conv kernel ===================================

static __device__ __forceinline__ void issue_halo(int tile, uint32_t dst, uint32_t mbar) {
    int nimg = tile / 49, r = tile % 49;
    int h0 = (r / 7) * 16, w0 = (r % 7) * 16;
    MBAR_EXPECT_TX(mbar, (unsigned)HALO_BYTES);
    const char* src = (const char*)g_xb + ((size_t)((nimg*HP + h0) * HP + w0)) * 128;
    #pragma unroll
    for (int rr = 0; rr < 18; rr++)
        BULK_G2S(dst + rr*2304, src + (size_t)rr * HP * 128, 2304u, mbar);
}

__global__ void __launch_bounds__(256, 1)
k_conv(const float* __restrict__ bias, float* __restrict__ out) {
    extern __shared__ char smem[];
    __shared__ unsigned s_t;
    const uint32_t sb = smem_u32(smem);
    const int tid = threadIdx.x, wid = tid >> 5, L = tid & 31;
    const int wm = wid >> 1, nh = wid & 1;       // 4 M-groups x 2 N-halves
    const int gid = L >> 2, tig = L & 3;
    const int mx  = L & 15;                      // lane's ldmatrix row (pixel col)
    const int chi = L >> 4;                      // k 16B-chunk half

    if (tid == 0) { MBAR_INIT(sb + OFF_MBAR, 1); MBAR_INIT(sb + OFF_MBAR + 8, 1); }
    __syncthreads();

    // grab first two tiles, issue their halos into the two buffers
    if (tid == 0) s_t = atomicAdd(&g_tile, 1u);
    __syncthreads();
    int t0 = (int)s_t;
    if (tid == 0 && t0 < NTILE) issue_halo(t0, sb + OFF_H0, sb + OFF_MBAR);
    __syncthreads();
    if (tid == 0) s_t = atomicAdd(&g_tile, 1u);
    __syncthreads();
    int t1 = (int)s_t;
    if (tid == 0 && t1 < NTILE) issue_halo(t1, sb + OFF_H1, sb + OFF_MBAR + 8);

    // B fragments -> smem (overlaps with in-flight halos)
    {
        const uint4* gb = (const uint4*)g_B;
        uint4* sB = (uint4*)smem;
        for (int i = tid; i < B_BYTES/16; i += 256) sB[i] = gb[i];
    }
    float bs[4][2];
    #pragma unroll
    for (int ncl = 0; ncl < 4; ncl++) {
        int n = (nh*4 + ncl)*8 + tig*2;
        bs[ncl][0] = bias[n]; bs[ncl][1] = bias[n+1];
    }
    __syncthreads();

    int ph0 = 0, ph1 = 0, buf = 0;
    while (t0 < NTILE) {
        if (buf == 0) { MBAR_WAIT(sb + OFF_MBAR,     ph0); ph0 ^= 1; }
        else          { MBAR_WAIT(sb + OFF_MBAR + 8, ph1); ph1 ^= 1; }
        const uint32_t hbase = sb + (buf ? OFF_H1 : OFF_H0);

        float acc[4][4][4];
        #pragma unroll
        for (int f = 0; f < 4; f++)
            #pragma unroll
            for (int c = 0; c < 4; c++)
                #pragma unroll
                for (int q = 0; q < 4; q++) acc[f][c][q] = 0.f;

        #pragma unroll 1
        for (int t = 0; t < 9; t++) {
            const int ky = t / 3, kx = t - ky*3;
            const int rk = (mx + kx) & 7;                 // rotation key
            const uint32_t rowbase = hbase
                + (uint32_t)(((wm*4 + ky)*18 + mx + kx) * 128);
            #pragma unroll
            for (int kc = 0; kc < 4; kc++) {
                const uint32_t col = (uint32_t)(((((kc<<1) | chi) ^ rk)) << 4);
                uint32_t a[4][4];
                #pragma unroll
                for (int f = 0; f < 4; f++)
                    LDSM_X4(a[f], rowbase + (uint32_t)(f*2304) + col);
                const uint32_t bb = sb
                    + (uint32_t)((((t*4 + kc)*4) + nh*2) * 512)
                    + (uint32_t)(L << 4);
                uint32_t b0x, b0y, b0z, b0w, b1x, b1y, b1z, b1w;
                LDS128(b0x, b0y, b0z, b0w, bb);
                LDS128(b1x, b1y, b1z, b1w, bb + 512);
                #pragma unroll
                for (int f = 0; f < 4; f++) {
                    MMA4(acc[f][0], a[f], b0x, b0y);
                    MMA4(acc[f][1], a[f], b0z, b0w);
                    MMA4(acc[f][2], a[f], b1x, b1y);
                    MMA4(acc[f][3], a[f], b1z, b1w);
                }
            }
        }

        // epilogue: bias + ReLU, streaming stores (out never re-read)
        {
            const int nimg = t0 / 49, r = t0 % 49;
            const int h0 = (r / 7) * 16, w0 = (r % 7) * 16;
            #pragma unroll
            for (int f = 0; f < 4; f++) {
                const int h = h0 + wm*4 + f;
                #pragma unroll
                for (int ncl = 0; ncl < 4; ncl++) {
                    const int n = (nh*4 + ncl)*8 + tig*2;
                    float* p0 = out + ((size_t)(nimg*64 + n)) * PIX
                                    + (size_t)h * WW + w0;
                    float v0 = acc[f][ncl][0] + bs[ncl][0];
                    float v1 = acc[f][ncl][1] + bs[ncl][1];
                    float v2 = acc[f][ncl][2] + bs[ncl][0];
                    float v3 = acc[f][ncl][3] + bs[ncl][1];
                    __stcs(&p0[gid],           v0 > 0.f ? v0 : 0.f);
                    __stcs(&p0[PIX + gid],     v1 > 0.f ? v1 : 0.f);
                    __stcs(&p0[gid + 8],       v2 > 0.f ? v2 : 0.f);
                    __stcs(&p0[PIX + gid + 8], v3 > 0.f ? v3 : 0.f);
                }
            }
        }

        // steal next tile; refill this buffer
        if (tid == 0) s_t = atomicAdd(&g_tile, 1u);
        __syncthreads();             // halo[buf] consumed + s_t visible
        int t2 = (int)s_t;
        if (tid == 0 && t2 < NTILE)
            issue_halo(t2, sb + (buf ? OFF_H1 : OFF_H0), sb + OFF_MBAR + buf*8);
        t0 = t1; t1 = t2; buf ^= 1;
    }
}

// ============================ launch ========================================
extern "C" void kernel_launch(void* const* d_in, const int* in_sizes, int n_in,
                              void* d_out, int out_size) {
    (void)in_sizes; (void)n_in; (void)out_size;
    const float* x     = (const float*)d_in[0];
    const float* gamma = (const float*)d_in[1];
    const float* beta  = (const float*)d_in[2];
    const float* Wt    = (const float*)d_in[3];
    const float* b     = (const float*)d_in[4];
    float* out = (float*)d_out;

    int sms = 148;
    cudaDeviceGetAttribute(&sms, cudaDevAttrMultiProcessorCount, 0);
    cudaFuncSetAttribute(k_conv, cudaFuncAttributeMaxDynamicSharedMemorySize, SMEM_TOTAL);

    k_stats<<<dim3(64, 32), 256>>>(x);
    k_final<<<1, 64>>>(gamma, beta);
    k_prep<<<18 + N_IMG*HP, 256>>>(x, Wt);
    k_conv<<<sms, 256, SMEM_TOTAL>>>(b, out);
}

// round 16
// speedup vs baseline: 1.0326x; 1.0326x over previous
#include <cuda_runtime.h>
#include <cuda_fp16.h>
#include <cstdint>
#include <cstddef>

// ============================================================================
// BinConv2d: BN(train stats) -> sign -> conv3x3(64->64,pad1) -> +bias -> ReLU
//   x:[32,64,112,112] f32 -> out same shape f32.
// sm_103-safe (harness compiles at compute_103: no tcgen05):
//   mma.sync.m16n8k16 f16 implicit GEMM (measured at its structural floor:
//   rt_eff ~13 cyc/SMSP for f32-acc HMMA on sm_103a; 6 identical measurements).
// 4 launches:
//   k_stats : per-(c,n) partials, 128-thr blocks -> 16 blocks/SM -> ALL 2048
//             blocks resident in ONE wave (kills the 1.68-wave quantization)
//   k_final : per-channel scale/shift + work-steal counter reset (~1us;
//             fusing it elsewhere measured slower 3x: R10/R12/R14)
//   k_prep  : blocks 0-17 wprep; rest binarize one row from g_ss (~20us)
//   k_conv  : persistent 256thr work-stealing conv (86us, mma.sync floor)
// ============================================================================

#define N_IMG 32
#define HH    112
#define WW    112
#define HP    114
#define PIX   (HH*WW)            // 12544
#define NTILE 1568               // 32 n * 7 th * 7 tw  (16x16 px tiles)

#define B_BYTES    73728         // 9 taps * 4 ksteps * 4 jpairs * 32 lanes * 16B
#define HALO_BYTES 41472         // 18 rows * 18 px * 128B
#define OFF_B      0
#define OFF_H0     (OFF_B + B_BYTES)       // 73728
#define OFF_H1     (OFF_H0 + HALO_BYTES)   // 115200
#define OFF_MBAR   (OFF_H1 + HALO_BYTES)   // 156672
#define SMEM_TOTAL (OFF_MBAR + 16)         // 156688

// ---- scratch (device globals; no runtime allocation) ----
__device__ __align__(1024) __half g_xb[(size_t)N_IMG*HP*HP*64]; // 53.2MB
__device__ __align__(1024) unsigned char g_B[B_BYTES];
__device__ float2 g_part[64*32];
__device__ float2 g_ss[64];
__device__ unsigned g_tile;

// ============================ PTX helpers ===================================
static __device__ __forceinline__ uint32_t smem_u32(const void* p) {
    uint32_t a;
    asm("{ .reg .u64 t; cvta.to.shared.u64 t, %1; cvt.u32.u64 %0, t; }"
        : "=r"(a) : "l"(p));
    return a;
}

#define MBAR_INIT(mbar, cnt) \
    asm volatile("mbarrier.init.shared.b64 [%0], %1;" :: "r"(mbar), "r"(cnt) : "memory")

#define MBAR_EXPECT_TX(mbar, bytes) \
    asm volatile("mbarrier.arrive.expect_tx.shared.b64 _, [%0], %1;" \
                 :: "r"(mbar), "r"(bytes) : "memory")

#define MBAR_WAIT(mbar, ph) do {                                            \
    asm volatile("{\n\t.reg .pred P;\n\t"                                   \
        "WL%=:\n\t"                                                         \
        "mbarrier.try_wait.parity.acquire.cta.shared::cta.b64 P, [%0], %1, 0x989680;\n\t" \
        "@P bra.uni WD%=;\n\t"                                              \
        "bra.uni WL%=;\n\t"                                                 \
        "WD%=:\n\t}"                                                        \
        :: "r"(mbar), "r"((unsigned)(ph)) : "memory");                      \
} while (0)

#define BULK_G2S(dst, src, size, mbar) \
    asm volatile("cp.async.bulk.shared::cta.global.mbarrier::complete_tx::bytes [%0], [%1], %2, [%3];" \
                 :: "r"(dst), "l"(src), "r"(size), "r"(mbar) : "memory")

#define LDSM_X4(r, addr) \
    asm volatile("ldmatrix.sync.aligned.m8n8.x4.shared.b16 {%0,%1,%2,%3}, [%4];" \
        : "=r"((r)[0]),"=r"((r)[1]),"=r"((r)[2]),"=r"((r)[3]) : "r"(addr))

#define LDS128(v0,v1,v2,v3,addr) \
    asm volatile("ld.shared.v4.b32 {%0,%1,%2,%3}, [%4];" \
        : "=r"(v0),"=r"(v1),"=r"(v2),"=r"(v3) : "r"(addr))

#define MMA4(d, a, b0, b1) \
    asm volatile("mma.sync.aligned.m16n8k16.row.col.f32.f16.f16.f32 " \
        "{%0,%1,%2,%3}, {%4,%5,%6,%7}, {%8,%9}, {%0,%1,%2,%3};" \
        : "+f"((d)[0]),"+f"((d)[1]),"+f"((d)[2]),"+f"((d)[3]) \
        : "r"((a)[0]),"r"((a)[1]),"r"((a)[2]),"r"((a)[3]), "r"(b0),"r"(b1))

// ============================ stats kernel ==================================
// 128 threads/block: 16 blocks/SM resident => all 2048 blocks in one wave.
// 4 independent load streams per batch; PIX/4 = 3136 = 24*128 + 64.

__global__ void __launch_bounds__(128)
k_stats(const float* __restrict__ x) {
    int c = blockIdx.x, n = blockIdx.y;
    const int tid = threadIdx.x;
    const float4* p = (const float4*)(x + ((size_t)(n*64 + c)) * PIX);

    float s0 = 0.f, s1 = 0.f, s2 = 0.f, s3 = 0.f;
    float q0 = 0.f, q1 = 0.f, q2 = 0.f, q3 = 0.f;
    #pragma unroll
    for (int b = 0; b < 6; b++) {
        const int i = b*512 + tid;
        float4 a0 = p[i], a1 = p[i+128], a2 = p[i+256], a3 = p[i+384];
        s0 += a0.x + a0.y + a0.z + a0.w;
        q0 += a0.x*a0.x + a0.y*a0.y + a0.z*a0.z + a0.w*a0.w;
        s1 += a1.x + a1.y + a1.z + a1.w;
        q1 += a1.x*a1.x + a1.y*a1.y + a1.z*a1.z + a1.w*a1.w;
        s2 += a2.x + a2.y + a2.z + a2.w;
        q2 += a2.x*a2.x + a2.y*a2.y + a2.z*a2.z + a2.w*a2.w;
        s3 += a3.x + a3.y + a3.z + a3.w;
        q3 += a3.x*a3.x + a3.y*a3.y + a3.z*a3.z + a3.w*a3.w;
    }
    if (tid < 64) {                                 // remainder: 3072..3135
        float4 r = p[3072 + tid];
        s0 += r.x + r.y + r.z + r.w;
        q0 += r.x*r.x + r.y*r.y + r.z*r.z + r.w*r.w;
    }
    float s = (s0 + s1) + (s2 + s3);
    float q = (q0 + q1) + (q2 + q3);
    #pragma unroll
    for (int o = 16; o > 0; o >>= 1) {
        s += __shfl_down_sync(0xFFFFFFFFu, s, o);
        q += __shfl_down_sync(0xFFFFFFFFu, q, o);
    }
    __shared__ float ws[4], wq[4];
    if ((tid & 31) == 0) { ws[tid >> 5] = s; wq[tid >> 5] = q; }
    __syncthreads();
    if (tid < 4) {
        s = ws[tid]; q = wq[tid];
        #pragma unroll
        for (int o = 2; o > 0; o >>= 1) {
            s += __shfl_down_sync(0xFu, s, o);
            q += __shfl_down_sync(0xFu, q, o);
        }
        if (tid == 0) g_part[c*32 + n] = make_float2(s, q);
    }
}

__global__ void k_final(const float* __restrict__ gamma, const float* __restrict__ beta) {
    int c = threadIdx.x;
    if (c == 0) g_tile = 0u;          // reset conv work-steal counter each replay
    if (c >= 64) return;
    float s = 0.f, q = 0.f;
    #pragma unroll 4
    for (int n = 0; n < 32; n++) { float2 p = g_part[c*32 + n]; s += p.x; q += p.y; }
    const float inv = 1.0f / (float)(32*PIX);
    float mean = s * inv;
    float var  = q * inv - mean*mean;     // biased var, matches reference
    float sc = gamma[c] / sqrtf(var + 1e-4f);
    g_ss[c] = make_float2(sc, beta[c] - mean*sc);
}

// ============================ prep kernel ===================================
// blocks 0..17: weight prep.  blocks 18..: binarize one padded row.

static __device__ __forceinline__ void wprep_unit(int u, int tid, const float* Wt) {
    int idx = u*256 + tid;
    int lane = idx & 31, j = (idx>>5)&3, kc = (idx>>7)&3, tap = idx>>9;
    int gid = lane >> 2, tig = lane & 3;
    uint32_t o4[4];
    #pragma unroll
    for (int s2 = 0; s2 < 2; s2++) {
        int n = (j*2 + s2)*8 + gid;
        #pragma unroll
        for (int p = 0; p < 2; p++) {
            uint32_t pr = 0;
            #pragma unroll
            for (int e = 0; e < 2; e++) {
                int kch = kc*16 + tig*2 + e + p*8;
                float w = Wt[((size_t)n*64 + kch)*9 + tap];
                __half v = __float2half(w);
                unsigned short us = *(unsigned short*)&v;
                pr |= (uint32_t)us << (e*16);
            }
            o4[s2*2 + p] = pr;
        }
    }
    *(uint4*)(g_B + (size_t)(((tap*4 + kc)*4 + j)*512) + (size_t)lane*16)
        = make_uint4(o4[0], o4[1], o4[2], o4[3]);
}

__global__ void __launch_bounds__(256)
k_prep(const float* __restrict__ x, const float* __restrict__ Wt) {
    const int tid = threadIdx.x;
    if (blockIdx.x < 18) { wprep_unit(blockIdx.x, tid, Wt); return; }

    const int v = blockIdx.x - 18;
    const int n = v / HP, hp = v % HP;
    uint32_t* dst = (uint32_t*)(g_xb + ((size_t)(n*HP + hp)) * HP * 64);
    if (hp == 0 || hp == HP-1) {
        for (int i = tid; i < HP*32; i += 256) dst[i] = 0u;
        return;
    }
    __shared__ float s[64][113];
    __shared__ float2 ss[64];
    if (tid < 64) ss[tid] = g_ss[tid];
    const int h = hp - 1;
    const float* src = x + ((size_t)n*64) * PIX + (size_t)h * WW;
    for (int i = tid; i < 64*WW; i += 256) {
        int c = i / WW, w = i % WW;
        s[c][w] = __ldcs(&src[(size_t)c * PIX + w]);   // streaming: protect L2
    }
    __syncthreads();
    if (tid < 64) {                       // zero border cols wp=0, wp=113
        int cp = tid & 31;
        int wp = (tid < 32) ? 0 : (HP-1);
        dst[wp*32 + cp] = 0u;
    }
    for (int i = tid; i < WW*32; i += 256) {
        int w = i >> 5, cp = i & 31, c = cp*2;
        float2 p0 = ss[c], p1 = ss[c+1];
        float v0 = s[c][w]   * p0.x + p0.y;
        float v1 = s[c+1][w] * p1.x + p1.y;
        uint32_t u0 = v0 > 0.f ? 0x3C00u : (v0 < 0.f ? 0xBC00u : 0u);  // fp16 +-1
        uint32_t u1 = v1 > 0.f ? 0x3C00u : (v1 < 0.f ? 0xBC00u : 0u);
        int wp = w + 1;
        int pos = (((cp>>2) ^ (wp & 7)) << 2) | (cp & 3);
        dst[wp*32 + pos] = u0 | (u1 << 16);
    }
}

// ============================ conv kernel ===================================

static __device__ __forceinline__ void issue_halo(int tile, uint32_t dst, uint32_t mbar) {
    int nimg = tile / 49, r = tile % 49;
    int h0 = (r / 7) * 16, w0 = (r % 7) * 16;
    MBAR_EXPECT_TX(mbar, (unsigned)HALO_BYTES);
    const char* src = (const char*)g_xb + ((size_t)((nimg*HP + h0) * HP + w0)) * 128;
    #pragma unroll
    for (int rr = 0; rr < 18; rr++)
        BULK_G2S(dst + rr*2304, src + (size_t)rr * HP * 128, 2304u, mbar);
}

__global__ void __launch_bounds__(256, 1)
k_conv(const float* __restrict__ bias, float* __restrict__ out) {
    extern __shared__ char smem[];
    __shared__ unsigned s_t;
    const uint32_t sb = smem_u32(smem);
    const int tid = threadIdx.x, wid = tid >> 5, L = tid & 31;
    const int wm = wid >> 1, nh = wid & 1;       // 4 M-groups x 2 N-halves
    const int gid = L >> 2, tig = L & 3;
    const int mx  = L & 15;                      // lane's ldmatrix row (pixel col)
    const int chi = L >> 4;                      // k 16B-chunk half

    if (tid == 0) { MBAR_INIT(sb + OFF_MBAR, 1); MBAR_INIT(sb + OFF_MBAR + 8, 1); }
    __syncthreads();

    // grab first two tiles, issue their halos into the two buffers
    if (tid == 0) s_t = atomicAdd(&g_tile, 1u);
    __syncthreads();
    int t0 = (int)s_t;
    if (tid == 0 && t0 < NTILE) issue_halo(t0, sb + OFF_H0, sb + OFF_MBAR);
    __syncthreads();
    if (tid == 0) s_t = atomicAdd(&g_tile, 1u);
    __syncthreads();
    int t1 = (int)s_t;
    if (tid == 0 && t1 < NTILE) issue_halo(t1, sb + OFF_H1, sb + OFF_MBAR + 8);

    // B fragments -> smem (overlaps with in-flight halos)
    {
        const uint4* gb = (const uint4*)g_B;
        uint4* sB = (uint4*)smem;
        for (int i = tid; i < B_BYTES/16; i += 256) sB[i] = gb[i];
    }
    float bs[4][2];
    #pragma unroll
    for (int ncl = 0; ncl < 4; ncl++) {
        int n = (nh*4 + ncl)*8 + tig*2;
        bs[ncl][0] = bias[n]; bs[ncl][1] = bias[n+1];
    }
    __syncthreads();

    int ph0 = 0, ph1 = 0, buf = 0;
    while (t0 < NTILE) {
        if (buf == 0) { MBAR_WAIT(sb + OFF_MBAR,     ph0); ph0 ^= 1; }
        else          { MBAR_WAIT(sb + OFF_MBAR + 8, ph1); ph1 ^= 1; }
        const uint32_t hbase = sb + (buf ? OFF_H1 : OFF_H0);

        float acc[4][4][4];
        #pragma unroll
        for (int f = 0; f < 4; f++)
            #pragma unroll
            for (int c = 0; c < 4; c++)
                #pragma unroll
                for (int q = 0; q < 4; q++) acc[f][c][q] = 0.f;

        #pragma unroll 1
        for (int t = 0; t < 9; t++) {
            const int ky = t / 3, kx = t - ky*3;
            const int rk = (mx + kx) & 7;                 // rotation key
            const uint32_t rowbase = hbase
                + (uint32_t)(((wm*4 + ky)*18 + mx + kx) * 128);
            #pragma unroll
            for (int kc = 0; kc < 4; kc++) {
                const uint32_t col = (uint32_t)(((((kc<<1) | chi) ^ rk)) << 4);
                uint32_t a[4][4];
                #pragma unroll
                for (int f = 0; f < 4; f++)
                    LDSM_X4(a[f], rowbase + (uint32_t)(f*2304) + col);
                const uint32_t bb = sb
                    + (uint32_t)((((t*4 + kc)*4) + nh*2) * 512)
                    + (uint32_t)(L << 4);
                uint32_t b0x, b0y, b0z, b0w, b1x, b1y, b1z, b1w;
                LDS128(b0x, b0y, b0z, b0w, bb);
                LDS128(b1x, b1y, b1z, b1w, bb + 512);
                #pragma unroll
                for (int f = 0; f < 4; f++) {
                    MMA4(acc[f][0], a[f], b0x, b0y);
                    MMA4(acc[f][1], a[f], b0z, b0w);
                    MMA4(acc[f][2], a[f], b1x, b1y);
                    MMA4(acc[f][3], a[f], b1z, b1w);
                }
            }
        }

        // epilogue: bias + ReLU, streaming stores (out never re-read)
        {
            const int nimg = t0 / 49, r = t0 % 49;
            const int h0 = (r / 7) * 16, w0 = (r % 7) * 16;
            #pragma unroll
            for (int f = 0; f < 4; f++) {
                const int h = h0 + wm*4 + f;
                #pragma unroll
                for (int ncl = 0; ncl < 4; ncl++) {
                    const int n = (nh*4 + ncl)*8 + tig*2;
                    float* p0 = out + ((size_t)(nimg*64 + n)) * PIX
                                    + (size_t)h * WW + w0;
                    float v0 = acc[f][ncl][0] + bs[ncl][0];
                    float v1 = acc[f][ncl][1] + bs[ncl][1];
                    float v2 = acc[f][ncl][2] + bs[ncl][0];
                    float v3 = acc[f][ncl][3] + bs[ncl][1];
                    __stcs(&p0[gid],           v0 > 0.f ? v0 : 0.f);
                    __stcs(&p0[PIX + gid],     v1 > 0.f ? v1 : 0.f);
                    __stcs(&p0[gid + 8],       v2 > 0.f ? v2 : 0.f);
                    __stcs(&p0[PIX + gid + 8], v3 > 0.f ? v3 : 0.f);
                }
            }
        }

        // steal next tile; refill this buffer
        if (tid == 0) s_t = atomicAdd(&g_tile, 1u);
        __syncthreads();             // halo[buf] consumed + s_t visible
        int t2 = (int)s_t;
        if (tid == 0 && t2 < NTILE)
            issue_halo(t2, sb + (buf ? OFF_H1 : OFF_H0), sb + OFF_MBAR + buf*8);
        t0 = t1; t1 = t2; buf ^= 1;
    }
}

// ============================ launch ========================================
extern "C" void kernel_launch(void* const* d_in, const int* in_sizes, int n_in,
                              void* d_out, int out_size) {
    (void)in_sizes; (void)n_in; (void)out_size;
    const float* x     = (const float*)d_in[0];
    const float* gamma = (const float*)d_in[1];
    const float* beta  = (const float*)d_in[2];
    const float* Wt    = (const float*)d_in[3];
    const float* b     = (const float*)d_in[4];
    float* out = (float*)d_out;

    int sms = 148;
    cudaDeviceGetAttribute(&sms, cudaDevAttrMultiProcessorCount, 0);
    cudaFuncSetAttribute(k_conv, cudaFuncAttributeMaxDynamicSharedMemorySize, SMEM_TOTAL);

    k_stats<<<dim3(64, 32), 128>>>(x);
    k_final<<<1, 64>>>(gamma, beta);
    k_prep<<<18 + N_IMG*HP, 256>>>(x, Wt);
    k_conv<<<sms, 256, SMEM_TOTAL>>>(b, out);
}